// round 4
// baseline (speedup 1.0000x reference)
#include <cuda_runtime.h>
#include <cuda_bf16.h>
#include <math.h>
#include <stdint.h>

// Shapes (fixed)
#define Bc   2
#define Lc   4096
#define Dc   1024
#define Hc   16
#define DHc  64
#define Mc   256
#define BHc  32
#define ROWS 8192   // B*L

// -------- scratch (device globals; no allocations allowed) --------
__device__ float g_q   [(size_t)ROWS * Dc];
__device__ float g_k   [(size_t)ROWS * Dc];
__device__ float g_v   [(size_t)ROWS * Dc];
__device__ float g_qf  [(size_t)BHc * Lc * Mc];
__device__ float g_kf  [(size_t)BHc * Lc * Mc];
__device__ float g_kv  [(size_t)BHc * Mc * DHc];
__device__ float g_ksum[(size_t)BHc * Mc];
__device__ float g_z   [(size_t)BHc * Lc];
__device__ float g_attn[(size_t)ROWS * Dc];
__device__ float g_y   [(size_t)ROWS * Dc];
__device__ __nv_bfloat16 g_ahi[(size_t)ROWS * Dc];
__device__ __nv_bfloat16 g_alo[(size_t)ROWS * Dc];
__device__ __nv_bfloat16 g_bthi[(size_t)Dc * Dc];
__device__ __nv_bfloat16 g_btlo[(size_t)Dc * Dc];

// ================= baseline-PTX tensor-core helpers (sm_80+, no 'a' features) ==========
__device__ __forceinline__ uint32_t smem_u32(const void* p) {
    uint32_t a;
    asm("{ .reg .u64 t; cvta.to.shared.u64 t, %1; cvt.u32.u64 %0, t; }"
        : "=r"(a) : "l"(p));
    return a;
}
__device__ __forceinline__ void cp_async16(uint32_t saddr, const void* g) {
    asm volatile("cp.async.cg.shared.global [%0], [%1], 16;"
                 :: "r"(saddr), "l"(g) : "memory");
}
#define CP_COMMIT() asm volatile("cp.async.commit_group;" ::: "memory")
#define CP_WAIT(n)  asm volatile("cp.async.wait_group %0;" :: "n"(n) : "memory")

__device__ __forceinline__ void ldsm_x4(uint32_t r[4], uint32_t addr) {
    asm volatile("ldmatrix.sync.aligned.m8n8.x4.shared.b16 {%0,%1,%2,%3}, [%4];"
                 : "=r"(r[0]), "=r"(r[1]), "=r"(r[2]), "=r"(r[3]) : "r"(addr));
}
__device__ __forceinline__ void mma16816(float c[4], const uint32_t a[4],
                                         uint32_t b0, uint32_t b1) {
    asm volatile(
        "mma.sync.aligned.m16n8k16.row.col.f32.bf16.bf16.f32 "
        "{%0,%1,%2,%3}, {%4,%5,%6,%7}, {%8,%9}, {%0,%1,%2,%3};"
        : "+f"(c[0]), "+f"(c[1]), "+f"(c[2]), "+f"(c[3])
        : "r"(a[0]), "r"(a[1]), "r"(a[2]), "r"(a[3]), "r"(b0), "r"(b1));
}

// ============================================================
// fp32 -> (hi, lo) bf16 split
// ============================================================
__global__ __launch_bounds__(256) void split_kernel(
    const float* __restrict__ in, __nv_bfloat16* __restrict__ hi,
    __nv_bfloat16* __restrict__ lo, int n4)
{
    int i = blockIdx.x * 256 + threadIdx.x;
    if (i >= n4) return;
    float4 v = ((const float4*)in)[i];
    __nv_bfloat16 h0 = __float2bfloat16_rn(v.x);
    __nv_bfloat16 h1 = __float2bfloat16_rn(v.y);
    __nv_bfloat16 h2 = __float2bfloat16_rn(v.z);
    __nv_bfloat16 h3 = __float2bfloat16_rn(v.w);
    __nv_bfloat16 l0 = __float2bfloat16_rn(v.x - __bfloat162float(h0));
    __nv_bfloat16 l1 = __float2bfloat16_rn(v.y - __bfloat162float(h1));
    __nv_bfloat16 l2 = __float2bfloat16_rn(v.z - __bfloat162float(h2));
    __nv_bfloat16 l3 = __float2bfloat16_rn(v.w - __bfloat162float(h3));
    ((__nv_bfloat162*)hi)[2*i]   = __halves2bfloat162(h0, h1);
    ((__nv_bfloat162*)hi)[2*i+1] = __halves2bfloat162(h2, h3);
    ((__nv_bfloat162*)lo)[2*i]   = __halves2bfloat162(l0, l1);
    ((__nv_bfloat162*)lo)[2*i+1] = __halves2bfloat162(l2, l3);
}

// ============================================================
// W [K=1024, N=1024] -> W^T [N,K] with bf16 hi/lo split
// ============================================================
__global__ void tsplit_kernel(const float* __restrict__ W,
    __nv_bfloat16* __restrict__ Thi, __nv_bfloat16* __restrict__ Tlo)
{
    __shared__ float t[32][33];
    int bx = blockIdx.x * 32, by = blockIdx.y * 32;
    int tx = threadIdx.x, ty = threadIdx.y;   // 32 x 8
#pragma unroll
    for (int i = 0; i < 32; i += 8)
        t[ty + i][tx] = W[(size_t)(by + ty + i) * Dc + bx + tx];
    __syncthreads();
#pragma unroll
    for (int i = 0; i < 32; i += 8) {
        float v = t[tx][ty + i];
        int orow = bx + ty + i, ocol = by + tx;
        __nv_bfloat16 h = __float2bfloat16_rn(v);
        Thi[(size_t)orow * Dc + ocol] = h;
        Tlo[(size_t)orow * Dc + ocol] = __float2bfloat16_rn(v - __bfloat162float(h));
    }
}

// ============================================================
// bf16x3 tensor-core GEMM via mma.sync (restructured R4):
// C[8192 x 1024] = alpha * A @ Bt^T (+optional exact GELU)
// CTA tile 128x128, 4 warps, warp tile 64x64, BK=32,
// 4-buffer / 3-deep cp.async pipeline, ONE __syncthreads per k-iter.
// 3 accumulation passes: Ah*Bh, Ah*Bl, Al*Bh.
// ============================================================
#define LDT 40                      // padded smem stride (bf16): 80B
#define GNIT 96                     // 3 passes * (1024/32)
#define STG_BYTES (128 * LDT * 2)   // one matrix buffer: 10240 B
#define GEMM_SMEM (4 * 2 * STG_BYTES)   // 4 stages x (A+B) = 81920 B

__global__ __launch_bounds__(128) void mma_gemm_kernel(
    const __nv_bfloat16* __restrict__ Ahi, const __nv_bfloat16* __restrict__ Alo,
    const __nv_bfloat16* __restrict__ Bhi, const __nv_bfloat16* __restrict__ Blo,
    float* __restrict__ C, float alpha, int do_gelu)
{
    extern __shared__ char gsm[];
    const int tid  = threadIdx.x;       // 0..127
    const int lane = tid & 31, wid = tid >> 5;   // 4 warps
    const int bm = blockIdx.y * 128;
    const int bn = blockIdx.x * 128;
    const int wm = (wid >> 1) * 64;     // warp row offset
    const int wn = (wid & 1) * 64;      // warp col offset

    uint32_t abase[4], bbase[4];
#pragma unroll
    for (int s = 0; s < 4; s++) {
        abase[s] = smem_u32(gsm + s * 2 * STG_BYTES);
        bbase[s] = abase[s] + STG_BYTES;
    }

    // ldmatrix lane addressing
    const int a_row = wm + (lane & 15);
    const int a_col = (lane >> 4) << 3;
    const int b_row = wn + (lane & 7) + ((lane >> 4) << 3);
    const int b_col = ((lane >> 3) & 1) << 3;

    // staging: 128 threads, each 4 x 16B per matrix
    const int g_row0 = tid >> 2;            // 0..31 (+32,+64,+96)
    const int g_c8   = (tid & 3) << 3;      // 0,8,16,24

    auto stage = [&](int kt) {
        const int s  = kt & 3;
        const int p  = kt >> 5;             // pass 0,1,2
        const int kk = (kt & 31) << 5;      // k element offset
        const __nv_bfloat16* Ag = (p < 2) ? Ahi : Alo;
        const __nv_bfloat16* Bg = (p == 1) ? Blo : Bhi;
#pragma unroll
        for (int i = 0; i < 4; i++) {
            int row = g_row0 + i * 32;
            uint32_t soff = (uint32_t)(row * LDT + g_c8) * 2;
            cp_async16(abase[s] + soff, Ag + (size_t)(bm + row) * Dc + kk + g_c8);
            cp_async16(bbase[s] + soff, Bg + (size_t)(bn + row) * Dc + kk + g_c8);
        }
        CP_COMMIT();
    };

    float acc[4][8][4];
#pragma unroll
    for (int mi = 0; mi < 4; mi++)
#pragma unroll
        for (int ni = 0; ni < 8; ni++)
#pragma unroll
            for (int e = 0; e < 4; e++) acc[mi][ni][e] = 0.f;

    stage(0); stage(1); stage(2);

    for (int kt = 0; kt < GNIT; kt++) {
        const int s = kt & 3;
        if (kt < GNIT - 2)      CP_WAIT(2);
        else if (kt == GNIT - 2) CP_WAIT(1);
        else                     CP_WAIT(0);
        __syncthreads();
        if (kt + 3 < GNIT) stage(kt + 3);   // writes buf (kt+3)&3 == (kt-1)&3, freed last iter

#pragma unroll
        for (int k0 = 0; k0 < 32; k0 += 16) {
            uint32_t a[4][4], b[4][4];
#pragma unroll
            for (int mi = 0; mi < 4; mi++)
                ldsm_x4(a[mi], abase[s] +
                        (uint32_t)((a_row + mi * 16) * LDT + k0 + a_col) * 2);
#pragma unroll
            for (int pr = 0; pr < 4; pr++)
                ldsm_x4(b[pr], bbase[s] +
                        (uint32_t)((b_row + pr * 16) * LDT + k0 + b_col) * 2);
#pragma unroll
            for (int mi = 0; mi < 4; mi++)
#pragma unroll
                for (int pr = 0; pr < 4; pr++) {
                    mma16816(acc[mi][2 * pr],     a[mi], b[pr][0], b[pr][1]);
                    mma16816(acc[mi][2 * pr + 1], a[mi], b[pr][2], b[pr][3]);
                }
        }
    }

    // epilogue: 64x64 warp tile
    const int orow = bm + wm + (lane >> 2);
    const int ocol = bn + wn + ((lane & 3) << 1);
#pragma unroll
    for (int mi = 0; mi < 4; mi++) {
#pragma unroll
        for (int ni = 0; ni < 8; ni++) {
            float v0 = acc[mi][ni][0] * alpha;
            float v1 = acc[mi][ni][1] * alpha;
            float v2 = acc[mi][ni][2] * alpha;
            float v3 = acc[mi][ni][3] * alpha;
            if (do_gelu) {
                v0 = 0.5f * v0 * (1.f + erff(v0 * 0.70710678118654752f));
                v1 = 0.5f * v1 * (1.f + erff(v1 * 0.70710678118654752f));
                v2 = 0.5f * v2 * (1.f + erff(v2 * 0.70710678118654752f));
                v3 = 0.5f * v3 * (1.f + erff(v3 * 0.70710678118654752f));
            }
            float* p0 = &C[(size_t)(orow + mi * 16) * Dc + ocol + ni * 8];
            float* p1 = &C[(size_t)(orow + mi * 16 + 8) * Dc + ocol + ni * 8];
            *(float2*)p0 = make_float2(v0, v1);
            *(float2*)p1 = make_float2(v2, v3);
        }
    }
}

// ============================================================
// FAVOR+ feature kernel (unchanged, passing since R1)
// ============================================================
#define FEAT_SMEM_FLOATS (32*65 + 256*65 + 32*257)

__global__ __launch_bounds__(256) void feature_kernel(
    const float* __restrict__ S, const float* __restrict__ proj,
    float* __restrict__ F)
{
    extern __shared__ float sm[];
    float* us   = sm;
    float* ps   = sm + 32 * 65;
    float* dash = sm + 32 * 65 + 256 * 65;

    const int bh = blockIdx.y;
    const int b = bh >> 4, h = bh & 15;
    const int l0 = blockIdx.x * 32;
    const int tid = threadIdx.x;

#pragma unroll
    for (int i = 0; i < 2; i++) {
        int s = tid + i * 256;
        int r = s >> 4;
        int c4 = (s & 15) << 2;
        float4 a = *(const float4*)&S[(size_t)(b * Lc + l0 + r) * Dc + h * DHc + c4];
        us[r * 65 + c4 + 0] = a.x; us[r * 65 + c4 + 1] = a.y;
        us[r * 65 + c4 + 2] = a.z; us[r * 65 + c4 + 3] = a.w;
    }
    const float* ph = proj + (size_t)h * Mc * DHc;
#pragma unroll
    for (int i = 0; i < 16; i++) {
        int s = tid + i * 256;
        int r = s >> 4;
        int c4 = (s & 15) << 2;
        float4 a = *(const float4*)&ph[r * 64 + c4];
        ps[r * 65 + c4 + 0] = a.x; ps[r * 65 + c4 + 1] = a.y;
        ps[r * 65 + c4 + 2] = a.z; ps[r * 65 + c4 + 3] = a.w;
    }
    __syncthreads();

    const int tr4 = (tid & 7) * 4;
    const int tm8 = (tid >> 3) * 8;
    float acc[4][8];
#pragma unroll
    for (int i = 0; i < 4; i++)
#pragma unroll
        for (int j = 0; j < 8; j++) acc[i][j] = 0.f;

#pragma unroll 8
    for (int d = 0; d < 64; d++) {
        float ur[4], pr[8];
#pragma unroll
        for (int i = 0; i < 4; i++) ur[i] = us[(tr4 + i) * 65 + d];
#pragma unroll
        for (int j = 0; j < 8; j++) pr[j] = ps[(tm8 + j) * 65 + d];
#pragma unroll
        for (int i = 0; i < 4; i++)
#pragma unroll
            for (int j = 0; j < 8; j++)
                acc[i][j] += ur[i] * pr[j];
    }
#pragma unroll
    for (int i = 0; i < 4; i++)
#pragma unroll
        for (int j = 0; j < 8; j++)
            dash[(tr4 + i) * 257 + tm8 + j] = acc[i][j];
    __syncthreads();

    const int w = tid >> 5, lane = tid & 31;
    for (int rr = w * 4; rr < w * 4 + 4; rr++) {
        float dv[8];
        float mx = -1e30f;
#pragma unroll
        for (int q = 0; q < 8; q++) {
            dv[q] = dash[rr * 257 + lane + q * 32];
            mx = fmaxf(mx, dv[q]);
        }
#pragma unroll
        for (int off = 16; off; off >>= 1)
            mx = fmaxf(mx, __shfl_xor_sync(0xffffffffu, mx, off));
        float u0 = us[rr * 65 + lane], u1 = us[rr * 65 + lane + 32];
        float dsq = u0 * u0 + u1 * u1;
#pragma unroll
        for (int off = 16; off; off >>= 1)
            dsq += __shfl_xor_sync(0xffffffffu, dsq, off);
        float base = -0.5f * dsq - mx;
        float* Fr = F + ((size_t)bh * Lc + l0 + rr) * Mc;
#pragma unroll
        for (int q = 0; q < 8; q++)
            Fr[lane + q * 32] = expf(dv[q] + base) * 0.0625f;
    }
}

// ============================================================
// kv / z / attn / ln_dup (unchanged, passing since R1)
// ============================================================
__global__ __launch_bounds__(256) void kv_kernel(
    const float* __restrict__ kf, const float* __restrict__ v,
    float* __restrict__ kv, float* __restrict__ ksum)
{
    __shared__ float vs[16][64];
    const int bh = blockIdx.x;
    const int b = bh >> 4, h = bh & 15;
    const int l0 = blockIdx.y * 256;
    const int t = threadIdx.x;

    float acc[64];
#pragma unroll
    for (int d = 0; d < 64; d++) acc[d] = 0.f;
    float s = 0.f;

    for (int l = l0; l < l0 + 256; l += 16) {
        {
            int r = t >> 4, c4 = (t & 15) << 2;
            *(float4*)&vs[r][c4] =
                *(const float4*)&v[(size_t)(b * Lc + l + r) * Dc + h * DHc + c4];
        }
        __syncthreads();
#pragma unroll
        for (int r = 0; r < 16; r++) {
            float a = kf[((size_t)bh * Lc + l + r) * Mc + t];
            s += a;
#pragma unroll
            for (int d4 = 0; d4 < 16; d4++) {
                float4 vv = *(const float4*)&vs[r][d4 * 4];
                acc[d4 * 4 + 0] += a * vv.x;
                acc[d4 * 4 + 1] += a * vv.y;
                acc[d4 * 4 + 2] += a * vv.z;
                acc[d4 * 4 + 3] += a * vv.w;
            }
        }
        __syncthreads();
    }
    float* kvp = kv + ((size_t)bh * Mc + t) * DHc;
#pragma unroll
    for (int d = 0; d < 64; d++) atomicAdd(&kvp[d], acc[d]);
    atomicAdd(&ksum[bh * Mc + t], s);
}

__global__ __launch_bounds__(256) void z_kernel(
    const float* __restrict__ qf, const float* __restrict__ ksum,
    float* __restrict__ z)
{
    __shared__ float ks[256];
    const int bh = blockIdx.y;
    ks[threadIdx.x] = ksum[bh * Mc + threadIdx.x];
    __syncthreads();
    const int w = threadIdx.x >> 5, lane = threadIdx.x & 31;
    const int l = blockIdx.x * 8 + w;
    const float* q = qf + ((size_t)bh * Lc + l) * Mc;
    float s = 0.f;
#pragma unroll
    for (int q8 = 0; q8 < 8; q8++) s += q[lane + q8 * 32] * ks[lane + q8 * 32];
#pragma unroll
    for (int off = 16; off; off >>= 1) s += __shfl_xor_sync(0xffffffffu, s, off);
    if (lane == 0) z[bh * Lc + l] = 1.0f / (s + 1e-6f);
}

__global__ __launch_bounds__(256) void attn_kernel(
    const float* __restrict__ qf, const float* __restrict__ kv,
    const float* __restrict__ z, float* __restrict__ attn)
{
    __shared__ float As2[32][132];
    __shared__ float Bs2[32][68];
    const int bh = blockIdx.y;
    const int b = bh >> 4, h = bh & 15;
    const int l0 = blockIdx.x * 128;
    const int tid = threadIdx.x;
    const int tr = (tid >> 3) * 4;
    const int tc = (tid & 7) * 8;

    const float* qfb = qf + ((size_t)bh * Lc + l0) * Mc;
    const float* kvb = kv + (size_t)bh * Mc * DHc;

    float acc[4][8];
#pragma unroll
    for (int i = 0; i < 4; i++)
#pragma unroll
        for (int j = 0; j < 8; j++) acc[i][j] = 0.f;

    for (int kk = 0; kk < 256; kk += 32) {
#pragma unroll
        for (int i = 0; i < 4; i++) {
            int s = tid + i * 256;
            int r = s >> 3;
            int c4 = (s & 7) << 2;
            float4 a = *(const float4*)&qfb[(size_t)r * Mc + kk + c4];
            As2[c4 + 0][r] = a.x; As2[c4 + 1][r] = a.y;
            As2[c4 + 2][r] = a.z; As2[c4 + 3][r] = a.w;
        }
#pragma unroll
        for (int i = 0; i < 2; i++) {
            int s = tid + i * 256;
            int r = s >> 4;
            int c4 = (s & 15) << 2;
            *(float4*)&Bs2[r][c4] = *(const float4*)&kvb[(size_t)(kk + r) * 64 + c4];
        }
        __syncthreads();
#pragma unroll
        for (int k = 0; k < 32; k++) {
            float4 a0 = *(const float4*)&As2[k][tr];
            float4 b0 = *(const float4*)&Bs2[k][tc];
            float4 b1 = *(const float4*)&Bs2[k][tc + 4];
            float ra[4] = {a0.x, a0.y, a0.z, a0.w};
            float rb[8] = {b0.x, b0.y, b0.z, b0.w, b1.x, b1.y, b1.z, b1.w};
#pragma unroll
            for (int i = 0; i < 4; i++)
#pragma unroll
                for (int j = 0; j < 8; j++)
                    acc[i][j] += ra[i] * rb[j];
        }
        __syncthreads();
    }
#pragma unroll
    for (int i = 0; i < 4; i++) {
        float zz = z[(size_t)bh * Lc + l0 + tr + i];
        float* ap = &attn[(size_t)(b * Lc + l0 + tr + i) * Dc + h * DHc + tc];
        *(float4*)&ap[0] = make_float4(acc[i][0]*zz, acc[i][1]*zz, acc[i][2]*zz, acc[i][3]*zz);
        *(float4*)&ap[4] = make_float4(acc[i][4]*zz, acc[i][5]*zz, acc[i][6]*zz, acc[i][7]*zz);
    }
}

__global__ __launch_bounds__(256) void ln_dup_kernel(
    const float* __restrict__ y, const float* __restrict__ g,
    const float* __restrict__ beta, float* __restrict__ out)
{
    __shared__ float red[18];
    const int row = blockIdx.x;
    const int b = row >> 12, l = row & 4095;
    const int tid = threadIdx.x;
    const float* yr = y + (size_t)row * Dc;

    float v[4];
    float s = 0.f, ss = 0.f;
#pragma unroll
    for (int i = 0; i < 4; i++) {
        float t = yr[tid + i * 256];
        v[i] = t; s += t; ss += t * t;
    }
#pragma unroll
    for (int off = 16; off; off >>= 1) {
        s  += __shfl_xor_sync(0xffffffffu, s, off);
        ss += __shfl_xor_sync(0xffffffffu, ss, off);
    }
    const int w = tid >> 5, lane = tid & 31;
    if (lane == 0) { red[w] = s; red[8 + w] = ss; }
    __syncthreads();
    if (tid == 0) {
        float ts = 0.f, tss = 0.f;
#pragma unroll
        for (int i = 0; i < 8; i++) { ts += red[i]; tss += red[8 + i]; }
        float mean = ts * (1.0f / 1024.0f);
        float var = tss * (1.0f / 1024.0f) - mean * mean;
        red[16] = mean;
        red[17] = rsqrtf(var + 1e-5f);
    }
    __syncthreads();
    const float mean = red[16], rstd = red[17];
    float* o0 = out + ((size_t)b * 8192 + 2 * (size_t)l) * Dc;
#pragma unroll
    for (int i = 0; i < 4; i++) {
        int c = tid + i * 256;
        float o = (v[i] - mean) * rstd * g[c] + beta[c];
        o0[c] = o;
        o0[Dc + c] = o;
    }
}

// ============================================================
// host launch
// ============================================================
extern "C" void kernel_launch(void* const* d_in, const int* in_sizes, int n_in,
                              void* d_out, int out_size)
{
    const float* x    = (const float*)d_in[0];
    const float* Wq   = (const float*)d_in[1];
    const float* Wk   = (const float*)d_in[2];
    const float* Wv   = (const float*)d_in[3];
    const float* Wo   = (const float*)d_in[4];
    const float* proj = (const float*)d_in[5];
    const float* ln_g = (const float*)d_in[6];
    const float* ln_b = (const float*)d_in[7];
    float* out = (float*)d_out;

    float *q, *k, *v, *qf, *kf, *kv, *ksum, *z, *attn, *y;
    __nv_bfloat16 *ahi, *alo, *bthi, *btlo;
    cudaGetSymbolAddress((void**)&q,    g_q);
    cudaGetSymbolAddress((void**)&k,    g_k);
    cudaGetSymbolAddress((void**)&v,    g_v);
    cudaGetSymbolAddress((void**)&qf,   g_qf);
    cudaGetSymbolAddress((void**)&kf,   g_kf);
    cudaGetSymbolAddress((void**)&kv,   g_kv);
    cudaGetSymbolAddress((void**)&ksum, g_ksum);
    cudaGetSymbolAddress((void**)&z,    g_z);
    cudaGetSymbolAddress((void**)&attn, g_attn);
    cudaGetSymbolAddress((void**)&y,    g_y);
    cudaGetSymbolAddress((void**)&ahi,  g_ahi);
    cudaGetSymbolAddress((void**)&alo,  g_alo);
    cudaGetSymbolAddress((void**)&bthi, g_bthi);
    cudaGetSymbolAddress((void**)&btlo, g_btlo);

    const float qscale = 0.35355339059327379f;  // 64^-0.25

    cudaFuncSetAttribute(mma_gemm_kernel,
                         cudaFuncAttributeMaxDynamicSharedMemorySize, GEMM_SMEM);
    const int feat_smem = FEAT_SMEM_FLOATS * (int)sizeof(float);
    cudaFuncSetAttribute(feature_kernel,
                         cudaFuncAttributeMaxDynamicSharedMemorySize, feat_smem);

    const int n4 = ROWS * Dc / 4;
    dim3 tgrid(32, 32), tblk(32, 8);
    dim3 ggrid(8, 64);   // N tiles x M tiles

    // split activations once (used by Q, K, V GEMMs)
    split_kernel<<<n4 / 256, 256>>>(x, ahi, alo, n4);

    tsplit_kernel<<<tgrid, tblk>>>(Wq, bthi, btlo);
    mma_gemm_kernel<<<ggrid, 128, GEMM_SMEM>>>(ahi, alo, bthi, btlo, q, qscale, 0);
    tsplit_kernel<<<tgrid, tblk>>>(Wk, bthi, btlo);
    mma_gemm_kernel<<<ggrid, 128, GEMM_SMEM>>>(ahi, alo, bthi, btlo, k, qscale, 0);
    tsplit_kernel<<<tgrid, tblk>>>(Wv, bthi, btlo);
    mma_gemm_kernel<<<ggrid, 128, GEMM_SMEM>>>(ahi, alo, bthi, btlo, v, 1.0f, 0);

    feature_kernel<<<dim3(Lc / 32, BHc), 256, feat_smem>>>(q, proj, qf);
    feature_kernel<<<dim3(Lc / 32, BHc), 256, feat_smem>>>(k, proj, kf);

    cudaMemsetAsync(kv,   0, (size_t)BHc * Mc * DHc * sizeof(float), 0);
    cudaMemsetAsync(ksum, 0, (size_t)BHc * Mc * sizeof(float), 0);
    kv_kernel<<<dim3(BHc, 16), 256>>>(kf, v, kv, ksum);

    z_kernel<<<dim3(Lc / 8, BHc), 256>>>(qf, ksum, z);
    attn_kernel<<<dim3(Lc / 128, BHc), 256>>>(qf, kv, z, attn);

    // O projection + exact GELU
    split_kernel<<<n4 / 256, 256>>>(attn, ahi, alo, n4);
    tsplit_kernel<<<tgrid, tblk>>>(Wo, bthi, btlo);
    mma_gemm_kernel<<<ggrid, 128, GEMM_SMEM>>>(ahi, alo, bthi, btlo, y, 1.0f, 1);

    ln_dup_kernel<<<ROWS, 256>>>(y, ln_g, ln_b, out);
}

// round 5
// speedup vs baseline: 1.1397x; 1.1397x over previous
#include <cuda_runtime.h>
#include <cuda_bf16.h>
#include <math.h>
#include <stdint.h>

// Shapes (fixed)
#define Bc   2
#define Lc   4096
#define Dc   1024
#define Hc   16
#define DHc  64
#define Mc   256
#define BHc  32
#define ROWS 8192   // B*L

// -------- scratch (device globals; no allocations allowed) --------
__device__ float g_v   [(size_t)ROWS * Dc];
__device__ float g_qf  [(size_t)BHc * Lc * Mc];
__device__ float g_kf  [(size_t)BHc * Lc * Mc];
__device__ float g_kv  [(size_t)BHc * Mc * DHc];
__device__ float g_ksum[(size_t)BHc * Mc];
__device__ float g_z   [(size_t)BHc * Lc];
__device__ float g_attn[(size_t)ROWS * Dc];
__device__ float g_y   [(size_t)ROWS * Dc];
__device__ __nv_bfloat16 g_ahi[(size_t)ROWS * Dc];
__device__ __nv_bfloat16 g_alo[(size_t)ROWS * Dc];
__device__ __nv_bfloat16 g_bthi[(size_t)Dc * Dc];
__device__ __nv_bfloat16 g_btlo[(size_t)Dc * Dc];
__device__ __nv_bfloat16 g_qhi[(size_t)ROWS * Dc];
__device__ __nv_bfloat16 g_qlo[(size_t)ROWS * Dc];
__device__ __nv_bfloat16 g_khi[(size_t)ROWS * Dc];
__device__ __nv_bfloat16 g_klo[(size_t)ROWS * Dc];
__device__ __nv_bfloat16 g_phi[(size_t)Hc * Mc * DHc];
__device__ __nv_bfloat16 g_plo[(size_t)Hc * Mc * DHc];

// ================= baseline-PTX tensor-core helpers (sm_80+) ==========
__device__ __forceinline__ uint32_t smem_u32(const void* p) {
    uint32_t a;
    asm("{ .reg .u64 t; cvta.to.shared.u64 t, %1; cvt.u32.u64 %0, t; }"
        : "=r"(a) : "l"(p));
    return a;
}
__device__ __forceinline__ void cp_async16(uint32_t saddr, const void* g) {
    asm volatile("cp.async.cg.shared.global [%0], [%1], 16;"
                 :: "r"(saddr), "l"(g) : "memory");
}
#define CP_COMMIT() asm volatile("cp.async.commit_group;" ::: "memory")
#define CP_WAIT(n)  asm volatile("cp.async.wait_group %0;" :: "n"(n) : "memory")

__device__ __forceinline__ void ldsm_x4(uint32_t r[4], uint32_t addr) {
    asm volatile("ldmatrix.sync.aligned.m8n8.x4.shared.b16 {%0,%1,%2,%3}, [%4];"
                 : "=r"(r[0]), "=r"(r[1]), "=r"(r[2]), "=r"(r[3]) : "r"(addr));
}
__device__ __forceinline__ void mma16816(float c[4], const uint32_t a[4],
                                         uint32_t b0, uint32_t b1) {
    asm volatile(
        "mma.sync.aligned.m16n8k16.row.col.f32.bf16.bf16.f32 "
        "{%0,%1,%2,%3}, {%4,%5,%6,%7}, {%8,%9}, {%0,%1,%2,%3};"
        : "+f"(c[0]), "+f"(c[1]), "+f"(c[2]), "+f"(c[3])
        : "r"(a[0]), "r"(a[1]), "r"(a[2]), "r"(a[3]), "r"(b0), "r"(b1));
}

// ============================================================
// fp32 -> (hi, lo) bf16 split
// ============================================================
__global__ __launch_bounds__(256) void split_kernel(
    const float* __restrict__ in, __nv_bfloat16* __restrict__ hi,
    __nv_bfloat16* __restrict__ lo, int n4)
{
    int i = blockIdx.x * 256 + threadIdx.x;
    if (i >= n4) return;
    float4 v = ((const float4*)in)[i];
    __nv_bfloat16 h0 = __float2bfloat16_rn(v.x);
    __nv_bfloat16 h1 = __float2bfloat16_rn(v.y);
    __nv_bfloat16 h2 = __float2bfloat16_rn(v.z);
    __nv_bfloat16 h3 = __float2bfloat16_rn(v.w);
    __nv_bfloat16 l0 = __float2bfloat16_rn(v.x - __bfloat162float(h0));
    __nv_bfloat16 l1 = __float2bfloat16_rn(v.y - __bfloat162float(h1));
    __nv_bfloat16 l2 = __float2bfloat16_rn(v.z - __bfloat162float(h2));
    __nv_bfloat16 l3 = __float2bfloat16_rn(v.w - __bfloat162float(h3));
    ((__nv_bfloat162*)hi)[2*i]   = __halves2bfloat162(h0, h1);
    ((__nv_bfloat162*)hi)[2*i+1] = __halves2bfloat162(h2, h3);
    ((__nv_bfloat162*)lo)[2*i]   = __halves2bfloat162(l0, l1);
    ((__nv_bfloat162*)lo)[2*i+1] = __halves2bfloat162(l2, l3);
}

// ============================================================
// W [K=1024, N=1024] -> W^T [N,K] with bf16 hi/lo split
// ============================================================
__global__ void tsplit_kernel(const float* __restrict__ W,
    __nv_bfloat16* __restrict__ Thi, __nv_bfloat16* __restrict__ Tlo)
{
    __shared__ float t[32][33];
    int bx = blockIdx.x * 32, by = blockIdx.y * 32;
    int tx = threadIdx.x, ty = threadIdx.y;   // 32 x 8
#pragma unroll
    for (int i = 0; i < 32; i += 8)
        t[ty + i][tx] = W[(size_t)(by + ty + i) * Dc + bx + tx];
    __syncthreads();
#pragma unroll
    for (int i = 0; i < 32; i += 8) {
        float v = t[tx][ty + i];
        int orow = bx + ty + i, ocol = by + tx;
        __nv_bfloat16 h = __float2bfloat16_rn(v);
        Thi[(size_t)orow * Dc + ocol] = h;
        Tlo[(size_t)orow * Dc + ocol] = __float2bfloat16_rn(v - __bfloat162float(h));
    }
}

// ============================================================
// bf16x3 tensor-core GEMM (exact R3 core, + output modes):
// omode 0: fp32 C;  1: fp32 C with exact GELU;  2: bf16 hi/lo split (Chi,Clo)
// CTA tile 128x128, BK=32, 2-buffer cp.async, 8 warps x (64x32 warp tile)
// ============================================================
#define LDT 40          // padded smem stride (bf16 elems): 80B
#define GNIT 96         // 3 passes * (1024/32)

__global__ __launch_bounds__(256) void mma_gemm_kernel(
    const __nv_bfloat16* __restrict__ Ahi, const __nv_bfloat16* __restrict__ Alo,
    const __nv_bfloat16* __restrict__ Bhi, const __nv_bfloat16* __restrict__ Blo,
    float* __restrict__ C, __nv_bfloat16* __restrict__ Chi,
    __nv_bfloat16* __restrict__ Clo, float alpha, int omode)
{
    __shared__ __nv_bfloat16 As[2][128 * LDT];
    __shared__ __nv_bfloat16 Bs[2][128 * LDT];

    const int tid  = threadIdx.x;
    const int lane = tid & 31, wid = tid >> 5;
    const int bm = blockIdx.y * 128;
    const int bn = blockIdx.x * 128;
    const int wm = (wid >> 2) * 64;
    const int wn = (wid & 3) * 32;

    const uint32_t as_base[2] = {smem_u32(As[0]), smem_u32(As[1])};
    const uint32_t bs_base[2] = {smem_u32(Bs[0]), smem_u32(Bs[1])};

    const int a_row = wm + (lane & 15);
    const int a_col = (lane >> 4) << 3;
    const int b_row = wn + (lane & 7) + ((lane >> 4) << 3);
    const int b_col = ((lane >> 3) & 1) << 3;

    const int g_row0 = tid >> 2;
    const int g_c8   = (tid & 3) << 3;

    auto stage = [&](int kt, int buf) {
        const int p  = kt >> 5;
        const int kk = (kt & 31) << 5;
        const __nv_bfloat16* Ag = (p < 2) ? Ahi : Alo;
        const __nv_bfloat16* Bg = (p == 1) ? Blo : Bhi;
#pragma unroll
        for (int i = 0; i < 2; i++) {
            int row = g_row0 + i * 64;
            uint32_t soff = (uint32_t)(row * LDT + g_c8) * 2;
            cp_async16(as_base[buf] + soff, Ag + (size_t)(bm + row) * Dc + kk + g_c8);
            cp_async16(bs_base[buf] + soff, Bg + (size_t)(bn + row) * Dc + kk + g_c8);
        }
        CP_COMMIT();
    };

    float acc[4][4][4];
#pragma unroll
    for (int mi = 0; mi < 4; mi++)
#pragma unroll
        for (int ni = 0; ni < 4; ni++)
#pragma unroll
            for (int e = 0; e < 4; e++) acc[mi][ni][e] = 0.f;

    stage(0, 0);
    stage(1, 1);

    for (int kt = 0; kt < GNIT; kt++) {
        const int buf = kt & 1;
        if (kt + 2 < GNIT) CP_WAIT(1); else CP_WAIT(0);
        __syncthreads();

#pragma unroll
        for (int k0 = 0; k0 < 32; k0 += 16) {
            uint32_t a[4][4];
#pragma unroll
            for (int mi = 0; mi < 4; mi++)
                ldsm_x4(a[mi], as_base[buf] +
                        (uint32_t)((a_row + mi * 16) * LDT + k0 + a_col) * 2);
            uint32_t b[2][4];
#pragma unroll
            for (int pr = 0; pr < 2; pr++)
                ldsm_x4(b[pr], bs_base[buf] +
                        (uint32_t)((b_row + pr * 16) * LDT + k0 + b_col) * 2);
#pragma unroll
            for (int mi = 0; mi < 4; mi++) {
                mma16816(acc[mi][0], a[mi], b[0][0], b[0][1]);
                mma16816(acc[mi][1], a[mi], b[0][2], b[0][3]);
                mma16816(acc[mi][2], a[mi], b[1][0], b[1][1]);
                mma16816(acc[mi][3], a[mi], b[1][2], b[1][3]);
            }
        }
        __syncthreads();
        if (kt + 2 < GNIT) stage(kt + 2, buf);
    }

    // epilogue: 64x32 warp tile
    const int orow = bm + wm + (lane >> 2);
    const int ocol = bn + wn + ((lane & 3) << 1);
#pragma unroll
    for (int mi = 0; mi < 4; mi++) {
#pragma unroll
        for (int ni = 0; ni < 4; ni++) {
            float v0 = acc[mi][ni][0] * alpha;
            float v1 = acc[mi][ni][1] * alpha;
            float v2 = acc[mi][ni][2] * alpha;
            float v3 = acc[mi][ni][3] * alpha;
            const size_t i0 = (size_t)(orow + mi * 16) * Dc + ocol + ni * 8;
            const size_t i1 = (size_t)(orow + mi * 16 + 8) * Dc + ocol + ni * 8;
            if (omode == 2) {
                __nv_bfloat16 h0 = __float2bfloat16_rn(v0);
                __nv_bfloat16 h1 = __float2bfloat16_rn(v1);
                __nv_bfloat16 h2 = __float2bfloat16_rn(v2);
                __nv_bfloat16 h3 = __float2bfloat16_rn(v3);
                *(__nv_bfloat162*)&Chi[i0] = __halves2bfloat162(h0, h1);
                *(__nv_bfloat162*)&Chi[i1] = __halves2bfloat162(h2, h3);
                *(__nv_bfloat162*)&Clo[i0] = __halves2bfloat162(
                    __float2bfloat16_rn(v0 - __bfloat162float(h0)),
                    __float2bfloat16_rn(v1 - __bfloat162float(h1)));
                *(__nv_bfloat162*)&Clo[i1] = __halves2bfloat162(
                    __float2bfloat16_rn(v2 - __bfloat162float(h2)),
                    __float2bfloat16_rn(v3 - __bfloat162float(h3)));
            } else {
                if (omode == 1) {
                    v0 = 0.5f * v0 * (1.f + erff(v0 * 0.70710678118654752f));
                    v1 = 0.5f * v1 * (1.f + erff(v1 * 0.70710678118654752f));
                    v2 = 0.5f * v2 * (1.f + erff(v2 * 0.70710678118654752f));
                    v3 = 0.5f * v3 * (1.f + erff(v3 * 0.70710678118654752f));
                }
                *(float2*)&C[i0] = make_float2(v0, v1);
                *(float2*)&C[i1] = make_float2(v2, v3);
            }
        }
    }
}

// ============================================================
// FAVOR+ feature via mma.sync bf16x3:
// For one (b,h), 128 L-rows x 256 M:
//   dash = u @ proj[h]^T (bf16x3), diag = 0.5|u|^2, rowmax over M,
//   F = __expf(dash - diag - rowmax) * M^-0.5
// 8 warps, warp tile 64x64 (2m x 4n warps). K=64, 3 passes.
// ============================================================
#define FLDK 72   // smem row stride (bf16): 144B, 16B multiple
#define FEAT2_SMEM ((128 + 128 + 256 + 256) * FLDK * 2 + 128 * 4 + 4 * 128 * 4)

__global__ __launch_bounds__(256) void feature_mma_kernel(
    const __nv_bfloat16* __restrict__ Uhi, const __nv_bfloat16* __restrict__ Ulo,
    const __nv_bfloat16* __restrict__ Phi, const __nv_bfloat16* __restrict__ Plo,
    float* __restrict__ F)
{
    extern __shared__ char fsm[];
    __nv_bfloat16* us_h = (__nv_bfloat16*)fsm;                    // [128][FLDK]
    __nv_bfloat16* us_l = us_h + 128 * FLDK;
    __nv_bfloat16* ps_h = us_l + 128 * FLDK;                      // [256][FLDK]
    __nv_bfloat16* ps_l = ps_h + 256 * FLDK;
    float* diag  = (float*)(ps_l + 256 * FLDK);                   // [128]
    float* rmaxp = diag + 128;                                    // [4][128]

    const int bh = blockIdx.y;
    const int b = bh >> 4, h = bh & 15;
    const int l0 = blockIdx.x * 128;
    const int tid = threadIdx.x;
    const int lane = tid & 31, wid = tid >> 5;

    // load u tiles (128 x 64, hi & lo)
#pragma unroll
    for (int i = 0; i < 4; i++) {
        int s = tid + i * 256;            // 0..1023
        int r = s >> 3, c8 = (s & 7) << 3;
        size_t gi = (size_t)(b * Lc + l0 + r) * Dc + h * DHc + c8;
        *(uint4*)&us_h[r * FLDK + c8] = *(const uint4*)&Uhi[gi];
        *(uint4*)&us_l[r * FLDK + c8] = *(const uint4*)&Ulo[gi];
    }
    // load proj[h] (256 x 64, hi & lo)
#pragma unroll
    for (int i = 0; i < 8; i++) {
        int s = tid + i * 256;            // 0..2047
        int r = s >> 3, c8 = (s & 7) << 3;
        size_t gi = (size_t)(h * Mc + r) * DHc + c8;
        *(uint4*)&ps_h[r * FLDK + c8] = *(const uint4*)&Phi[gi];
        *(uint4*)&ps_l[r * FLDK + c8] = *(const uint4*)&Plo[gi];
    }
    __syncthreads();

    // diag[r] = 0.5 * sum_d u^2  (u = hi + lo)
    if (tid < 128) {
        float s = 0.f;
#pragma unroll
        for (int d2 = 0; d2 < 32; d2++) {
            __nv_bfloat162 hh = *(__nv_bfloat162*)&us_h[tid * FLDK + d2 * 2];
            __nv_bfloat162 ll = *(__nv_bfloat162*)&us_l[tid * FLDK + d2 * 2];
            float u0 = __bfloat162float(hh.x) + __bfloat162float(ll.x);
            float u1 = __bfloat162float(hh.y) + __bfloat162float(ll.y);
            s += u0 * u0 + u1 * u1;
        }
        diag[tid] = 0.5f * s;
    }

    // mma: warp tile 64x64
    const int wm = (wid >> 2) * 64;
    const int wn = (wid & 3) * 64;
    const int a_row = wm + (lane & 15);
    const int a_col = (lane >> 4) << 3;
    const int b_row = wn + (lane & 7) + ((lane >> 4) << 3);
    const int b_col = ((lane >> 3) & 1) << 3;

    float acc[4][8][4];
#pragma unroll
    for (int mi = 0; mi < 4; mi++)
#pragma unroll
        for (int ni = 0; ni < 8; ni++)
#pragma unroll
            for (int e = 0; e < 4; e++) acc[mi][ni][e] = 0.f;

    const uint32_t ush = smem_u32(us_h), usl = smem_u32(us_l);
    const uint32_t psh = smem_u32(ps_h), psl = smem_u32(ps_l);
    __syncthreads();   // diag + smem tiles ready

#pragma unroll
    for (int p = 0; p < 3; p++) {
        const uint32_t ab = (p < 2) ? ush : usl;
        const uint32_t bb = (p == 1) ? psl : psh;
#pragma unroll
        for (int k0 = 0; k0 < 64; k0 += 16) {
            uint32_t a[4][4], bfr[4][4];
#pragma unroll
            for (int mi = 0; mi < 4; mi++)
                ldsm_x4(a[mi], ab + (uint32_t)((a_row + mi * 16) * FLDK + k0 + a_col) * 2);
#pragma unroll
            for (int pr = 0; pr < 4; pr++)
                ldsm_x4(bfr[pr], bb + (uint32_t)((b_row + pr * 16) * FLDK + k0 + b_col) * 2);
#pragma unroll
            for (int mi = 0; mi < 4; mi++)
#pragma unroll
                for (int pr = 0; pr < 4; pr++) {
                    mma16816(acc[mi][2 * pr],     a[mi], bfr[pr][0], bfr[pr][1]);
                    mma16816(acc[mi][2 * pr + 1], a[mi], bfr[pr][2], bfr[pr][3]);
                }
        }
    }

    // per-thread row maxima -> quad shuffle -> smem partials per n-warp
    float tmax[4][2];
#pragma unroll
    for (int mi = 0; mi < 4; mi++) {
        float m0 = -1e30f, m1 = -1e30f;
#pragma unroll
        for (int ni = 0; ni < 8; ni++) {
            m0 = fmaxf(m0, fmaxf(acc[mi][ni][0], acc[mi][ni][1]));
            m1 = fmaxf(m1, fmaxf(acc[mi][ni][2], acc[mi][ni][3]));
        }
#pragma unroll
        for (int off = 1; off <= 2; off <<= 1) {
            m0 = fmaxf(m0, __shfl_xor_sync(0xffffffffu, m0, off));
            m1 = fmaxf(m1, __shfl_xor_sync(0xffffffffu, m1, off));
        }
        tmax[mi][0] = m0; tmax[mi][1] = m1;
    }
    if ((lane & 3) == 0) {
        const int slab = wid & 3;
#pragma unroll
        for (int mi = 0; mi < 4; mi++) {
            int r = wm + mi * 16 + (lane >> 2);
            rmaxp[slab * 128 + r]     = tmax[mi][0];
            // row + 8 handled below with same slab
            rmaxp[slab * 128 + r + 8] = tmax[mi][1];
        }
    }
    __syncthreads();

    // epilogue: exp and store
#pragma unroll
    for (int mi = 0; mi < 4; mi++) {
        const int r0 = wm + mi * 16 + (lane >> 2);
        const int r1 = r0 + 8;
        float rm0 = fmaxf(fmaxf(rmaxp[r0], rmaxp[128 + r0]),
                          fmaxf(rmaxp[256 + r0], rmaxp[384 + r0]));
        float rm1 = fmaxf(fmaxf(rmaxp[r1], rmaxp[128 + r1]),
                          fmaxf(rmaxp[256 + r1], rmaxp[384 + r1]));
        const float base0 = -diag[r0] - rm0;
        const float base1 = -diag[r1] - rm1;
        float* F0 = F + ((size_t)bh * Lc + l0 + r0) * Mc;
        float* F1 = F + ((size_t)bh * Lc + l0 + r1) * Mc;
        const int c0 = wn + ((lane & 3) << 1);
#pragma unroll
        for (int ni = 0; ni < 8; ni++) {
            int c = c0 + ni * 8;
            *(float2*)&F0[c] = make_float2(
                __expf(acc[mi][ni][0] + base0) * 0.0625f,
                __expf(acc[mi][ni][1] + base0) * 0.0625f);
            *(float2*)&F1[c] = make_float2(
                __expf(acc[mi][ni][2] + base1) * 0.0625f,
                __expf(acc[mi][ni][3] + base1) * 0.0625f);
        }
    }
}

// ============================================================
// kv / z / attn / ln_dup (unchanged, passing since R1)
// ============================================================
__global__ __launch_bounds__(256) void kv_kernel(
    const float* __restrict__ kf, const float* __restrict__ v,
    float* __restrict__ kv, float* __restrict__ ksum)
{
    __shared__ float vs[16][64];
    const int bh = blockIdx.x;
    const int b = bh >> 4, h = bh & 15;
    const int l0 = blockIdx.y * 256;
    const int t = threadIdx.x;

    float acc[64];
#pragma unroll
    for (int d = 0; d < 64; d++) acc[d] = 0.f;
    float s = 0.f;

    for (int l = l0; l < l0 + 256; l += 16) {
        {
            int r = t >> 4, c4 = (t & 15) << 2;
            *(float4*)&vs[r][c4] =
                *(const float4*)&v[(size_t)(b * Lc + l + r) * Dc + h * DHc + c4];
        }
        __syncthreads();
#pragma unroll
        for (int r = 0; r < 16; r++) {
            float a = kf[((size_t)bh * Lc + l + r) * Mc + t];
            s += a;
#pragma unroll
            for (int d4 = 0; d4 < 16; d4++) {
                float4 vv = *(const float4*)&vs[r][d4 * 4];
                acc[d4 * 4 + 0] += a * vv.x;
                acc[d4 * 4 + 1] += a * vv.y;
                acc[d4 * 4 + 2] += a * vv.z;
                acc[d4 * 4 + 3] += a * vv.w;
            }
        }
        __syncthreads();
    }
    float* kvp = kv + ((size_t)bh * Mc + t) * DHc;
#pragma unroll
    for (int d = 0; d < 64; d++) atomicAdd(&kvp[d], acc[d]);
    atomicAdd(&ksum[bh * Mc + t], s);
}

__global__ __launch_bounds__(256) void z_kernel(
    const float* __restrict__ qf, const float* __restrict__ ksum,
    float* __restrict__ z)
{
    __shared__ float ks[256];
    const int bh = blockIdx.y;
    ks[threadIdx.x] = ksum[bh * Mc + threadIdx.x];
    __syncthreads();
    const int w = threadIdx.x >> 5, lane = threadIdx.x & 31;
    const int l = blockIdx.x * 8 + w;
    const float* q = qf + ((size_t)bh * Lc + l) * Mc;
    float s = 0.f;
#pragma unroll
    for (int q8 = 0; q8 < 8; q8++) s += q[lane + q8 * 32] * ks[lane + q8 * 32];
#pragma unroll
    for (int off = 16; off; off >>= 1) s += __shfl_xor_sync(0xffffffffu, s, off);
    if (lane == 0) z[bh * Lc + l] = 1.0f / (s + 1e-6f);
}

__global__ __launch_bounds__(256) void attn_kernel(
    const float* __restrict__ qf, const float* __restrict__ kv,
    const float* __restrict__ z, float* __restrict__ attn)
{
    __shared__ float As2[32][132];
    __shared__ float Bs2[32][68];
    const int bh = blockIdx.y;
    const int b = bh >> 4, h = bh & 15;
    const int l0 = blockIdx.x * 128;
    const int tid = threadIdx.x;
    const int tr = (tid >> 3) * 4;
    const int tc = (tid & 7) * 8;

    const float* qfb = qf + ((size_t)bh * Lc + l0) * Mc;
    const float* kvb = kv + (size_t)bh * Mc * DHc;

    float acc[4][8];
#pragma unroll
    for (int i = 0; i < 4; i++)
#pragma unroll
        for (int j = 0; j < 8; j++) acc[i][j] = 0.f;

    for (int kk = 0; kk < 256; kk += 32) {
#pragma unroll
        for (int i = 0; i < 4; i++) {
            int s = tid + i * 256;
            int r = s >> 3;
            int c4 = (s & 7) << 2;
            float4 a = *(const float4*)&qfb[(size_t)r * Mc + kk + c4];
            As2[c4 + 0][r] = a.x; As2[c4 + 1][r] = a.y;
            As2[c4 + 2][r] = a.z; As2[c4 + 3][r] = a.w;
        }
#pragma unroll
        for (int i = 0; i < 2; i++) {
            int s = tid + i * 256;
            int r = s >> 4;
            int c4 = (s & 15) << 2;
            *(float4*)&Bs2[r][c4] = *(const float4*)&kvb[(size_t)(kk + r) * 64 + c4];
        }
        __syncthreads();
#pragma unroll
        for (int k = 0; k < 32; k++) {
            float4 a0 = *(const float4*)&As2[k][tr];
            float4 b0 = *(const float4*)&Bs2[k][tc];
            float4 b1 = *(const float4*)&Bs2[k][tc + 4];
            float ra[4] = {a0.x, a0.y, a0.z, a0.w};
            float rb[8] = {b0.x, b0.y, b0.z, b0.w, b1.x, b1.y, b1.z, b1.w};
#pragma unroll
            for (int i = 0; i < 4; i++)
#pragma unroll
                for (int j = 0; j < 8; j++)
                    acc[i][j] += ra[i] * rb[j];
        }
        __syncthreads();
    }
#pragma unroll
    for (int i = 0; i < 4; i++) {
        float zz = z[(size_t)bh * Lc + l0 + tr + i];
        float* ap = &attn[(size_t)(b * Lc + l0 + tr + i) * Dc + h * DHc + tc];
        *(float4*)&ap[0] = make_float4(acc[i][0]*zz, acc[i][1]*zz, acc[i][2]*zz, acc[i][3]*zz);
        *(float4*)&ap[4] = make_float4(acc[i][4]*zz, acc[i][5]*zz, acc[i][6]*zz, acc[i][7]*zz);
    }
}

__global__ __launch_bounds__(256) void ln_dup_kernel(
    const float* __restrict__ y, const float* __restrict__ g,
    const float* __restrict__ beta, float* __restrict__ out)
{
    __shared__ float red[18];
    const int row = blockIdx.x;
    const int b = row >> 12, l = row & 4095;
    const int tid = threadIdx.x;
    const float* yr = y + (size_t)row * Dc;

    float v[4];
    float s = 0.f, ss = 0.f;
#pragma unroll
    for (int i = 0; i < 4; i++) {
        float t = yr[tid + i * 256];
        v[i] = t; s += t; ss += t * t;
    }
#pragma unroll
    for (int off = 16; off; off >>= 1) {
        s  += __shfl_xor_sync(0xffffffffu, s, off);
        ss += __shfl_xor_sync(0xffffffffu, ss, off);
    }
    const int w = tid >> 5, lane = tid & 31;
    if (lane == 0) { red[w] = s; red[8 + w] = ss; }
    __syncthreads();
    if (tid == 0) {
        float ts = 0.f, tss = 0.f;
#pragma unroll
        for (int i = 0; i < 8; i++) { ts += red[i]; tss += red[8 + i]; }
        float mean = ts * (1.0f / 1024.0f);
        float var = tss * (1.0f / 1024.0f) - mean * mean;
        red[16] = mean;
        red[17] = rsqrtf(var + 1e-5f);
    }
    __syncthreads();
    const float mean = red[16], rstd = red[17];
    float* o0 = out + ((size_t)b * 8192 + 2 * (size_t)l) * Dc;
#pragma unroll
    for (int i = 0; i < 4; i++) {
        int c = tid + i * 256;
        float o = (v[i] - mean) * rstd * g[c] + beta[c];
        o0[c] = o;
        o0[Dc + c] = o;
    }
}

// ============================================================
// host launch
// ============================================================
extern "C" void kernel_launch(void* const* d_in, const int* in_sizes, int n_in,
                              void* d_out, int out_size)
{
    const float* x    = (const float*)d_in[0];
    const float* Wq   = (const float*)d_in[1];
    const float* Wk   = (const float*)d_in[2];
    const float* Wv   = (const float*)d_in[3];
    const float* Wo   = (const float*)d_in[4];
    const float* proj = (const float*)d_in[5];
    const float* ln_g = (const float*)d_in[6];
    const float* ln_b = (const float*)d_in[7];
    float* out = (float*)d_out;

    float *v, *qf, *kf, *kv, *ksum, *z, *attn, *y;
    __nv_bfloat16 *ahi, *alo, *bthi, *btlo, *qhi, *qlo, *khi, *klo, *phi, *plo;
    cudaGetSymbolAddress((void**)&v,    g_v);
    cudaGetSymbolAddress((void**)&qf,   g_qf);
    cudaGetSymbolAddress((void**)&kf,   g_kf);
    cudaGetSymbolAddress((void**)&kv,   g_kv);
    cudaGetSymbolAddress((void**)&ksum, g_ksum);
    cudaGetSymbolAddress((void**)&z,    g_z);
    cudaGetSymbolAddress((void**)&attn, g_attn);
    cudaGetSymbolAddress((void**)&y,    g_y);
    cudaGetSymbolAddress((void**)&ahi,  g_ahi);
    cudaGetSymbolAddress((void**)&alo,  g_alo);
    cudaGetSymbolAddress((void**)&bthi, g_bthi);
    cudaGetSymbolAddress((void**)&btlo, g_btlo);
    cudaGetSymbolAddress((void**)&qhi,  g_qhi);
    cudaGetSymbolAddress((void**)&qlo,  g_qlo);
    cudaGetSymbolAddress((void**)&khi,  g_khi);
    cudaGetSymbolAddress((void**)&klo,  g_klo);
    cudaGetSymbolAddress((void**)&phi,  g_phi);
    cudaGetSymbolAddress((void**)&plo,  g_plo);

    const float qscale = 0.35355339059327379f;  // 64^-0.25

    cudaFuncSetAttribute(feature_mma_kernel,
                         cudaFuncAttributeMaxDynamicSharedMemorySize, FEAT2_SMEM);

    const int n4 = ROWS * Dc / 4;
    dim3 tgrid(32, 32), tblk(32, 8);
    dim3 ggrid(8, 64);

    // split x activations + proj (independent of GEMMs)
    split_kernel<<<n4 / 256, 256>>>(x, ahi, alo, n4);
    split_kernel<<<(Hc * Mc * DHc / 4) / 256, 256>>>(proj, phi, plo, Hc * Mc * DHc / 4);

    // Q, K (bf16 hi/lo out), V (fp32 out)
    tsplit_kernel<<<tgrid, tblk>>>(Wq, bthi, btlo);
    mma_gemm_kernel<<<ggrid, 256>>>(ahi, alo, bthi, btlo, nullptr, qhi, qlo, qscale, 2);
    tsplit_kernel<<<tgrid, tblk>>>(Wk, bthi, btlo);
    mma_gemm_kernel<<<ggrid, 256>>>(ahi, alo, bthi, btlo, nullptr, khi, klo, qscale, 2);
    tsplit_kernel<<<tgrid, tblk>>>(Wv, bthi, btlo);
    mma_gemm_kernel<<<ggrid, 256>>>(ahi, alo, bthi, btlo, v, nullptr, nullptr, 1.0f, 0);

    // features via tensor cores
    feature_mma_kernel<<<dim3(Lc / 128, BHc), 256, FEAT2_SMEM>>>(qhi, qlo, phi, plo, qf);
    feature_mma_kernel<<<dim3(Lc / 128, BHc), 256, FEAT2_SMEM>>>(khi, klo, phi, plo, kf);

    cudaMemsetAsync(kv,   0, (size_t)BHc * Mc * DHc * sizeof(float), 0);
    cudaMemsetAsync(ksum, 0, (size_t)BHc * Mc * sizeof(float), 0);
    kv_kernel<<<dim3(BHc, 16), 256>>>(kf, v, kv, ksum);

    z_kernel<<<dim3(Lc / 8, BHc), 256>>>(qf, ksum, z);
    attn_kernel<<<dim3(Lc / 128, BHc), 256>>>(qf, kv, z, attn);

    // O projection + exact GELU
    split_kernel<<<n4 / 256, 256>>>(attn, ahi, alo, n4);
    tsplit_kernel<<<tgrid, tblk>>>(Wo, bthi, btlo);
    mma_gemm_kernel<<<ggrid, 256>>>(ahi, alo, bthi, btlo, y, nullptr, nullptr, 1.0f, 1);

    ln_dup_kernel<<<ROWS, 256>>>(y, ln_g, ln_b, out);
}